// round 1
// baseline (speedup 1.0000x reference)
#include <cuda_runtime.h>
#include <math.h>

#define D_ 512
#define M_ 1200
#define B_ 4
#define L_ 2048
#define NROWS 8192
#define EPSV 1e-5f

#define OUT3_ELEMS (NROWS * D_)          /* 4194304  */
#define SM_ELEMS   (B_ * 6 * L_ * L_)    /* 100663296 */

// ---- static device scratch (no allocations allowed) ----
__device__ float g_v[B_ * M_];
__device__ float g_o[B_ * D_];
__device__ float g_beff[D_];
__device__ float g_beffpart[16 * D_];
__device__ float g_Wpart[4 * D_ * D_];
__device__ float g_Weff[D_ * D_];

// ============================================================
// sm output is exactly uniform 1/2048 everywhere (softmax of a
// row-constant logits matrix). Fill it.
// ============================================================
__global__ void fill_sm(float* __restrict__ out) {
    const float v = 1.0f / 2048.0f;
    float4 f = make_float4(v, v, v, v);
    float4* p = (float4*)(out + OUT3_ELEMS);
    int n4 = SM_ELEMS / 4;
    for (int i = blockIdx.x * blockDim.x + threadIdx.x; i < n4;
         i += gridDim.x * blockDim.x)
        p[i] = f;
}

// ============================================================
// v_b[j] = keyval[b] . Wkv[:, M+j] + bkv[M+j]   (V half only)
// ============================================================
__global__ void compute_v(const float* __restrict__ keyval,
                          const float* __restrict__ Wkv,
                          const float* __restrict__ bkv) {
    __shared__ float kv_s[D_];
    int b = blockIdx.y;
    for (int i = threadIdx.x; i < D_; i += blockDim.x)
        kv_s[i] = keyval[b * D_ + i];
    __syncthreads();
    int j = blockIdx.x * blockDim.x + threadIdx.x;
    if (j >= M_) return;
    const float* w = Wkv + M_ + j;  // column (M+j), row stride 2M
    float acc = bkv[M_ + j];
#pragma unroll 8
    for (int d = 0; d < D_; d++) acc += kv_s[d] * w[d * (2 * M_)];
    g_v[b * M_ + j] = acc;
}

// ============================================================
// o_b[c] = v_b . Wff[:, c] + bff[c]
// ============================================================
__global__ void compute_o(const float* __restrict__ Wff,
                          const float* __restrict__ bff) {
    __shared__ float v_s[M_];
    int b = blockIdx.y;
    for (int i = threadIdx.x; i < M_; i += blockDim.x)
        v_s[i] = g_v[b * M_ + i];
    __syncthreads();
    int c = blockIdx.x * blockDim.x + threadIdx.x;  // blockDim=256, grid.x=2
    float acc = bff[c];
#pragma unroll 8
    for (int j = 0; j < M_; j++) acc += v_s[j] * Wff[j * D_ + c];
    g_o[b * D_ + c] = acc;
}

// ============================================================
// b_eff partials: b_eff[c] = b2a . W2b[:, c] + b2b[c]  (split-K 16)
// ============================================================
__global__ void beff_part(const float* __restrict__ b2a,
                          const float* __restrict__ W2b) {
    __shared__ float s[128];
    int kz = blockIdx.x;   // 0..15
    int c = threadIdx.x;   // 0..511
    for (int i = threadIdx.x; i < 128; i += blockDim.x)
        s[i] = b2a[kz * 128 + i];
    __syncthreads();
    float acc = 0.0f;
#pragma unroll 8
    for (int k = 0; k < 128; k++)
        acc += s[k] * W2b[(kz * 128 + k) * D_ + c];
    g_beffpart[kz * D_ + c] = acc;
}

// ============================================================
// W_eff = W2a[512,2048] @ W2b[2048,512], deterministic split-K (4)
// 64x64 tiles, 256 threads, 4x4 per thread, BK=16
// ============================================================
__global__ void __launch_bounds__(256) weff_part(const float* __restrict__ W2a,
                                                 const float* __restrict__ W2b) {
    __shared__ float As[64][16];
    __shared__ float Bs[16][64];
    int t = threadIdx.x;
    int tx = t & 15, ty = t >> 4;
    int i0 = blockIdx.y * 64, o0 = blockIdx.x * 64, k0 = blockIdx.z * 512;
    float acc[4][4] = {};

    for (int kt = 0; kt < 512; kt += 16) {
#pragma unroll
        for (int it = 0; it < 4; it++) {
            int i = (t >> 4) + 16 * it;
            int k = t & 15;
            As[i][k] = W2a[(size_t)(i0 + i) * 2048 + k0 + kt + k];
        }
#pragma unroll
        for (int it = 0; it < 4; it++) {
            int k = (t >> 6) + 4 * it;
            int o = t & 63;
            Bs[k][o] = W2b[(size_t)(k0 + kt + k) * D_ + o0 + o];
        }
        __syncthreads();
#pragma unroll
        for (int k = 0; k < 16; k++) {
            float a[4];
#pragma unroll
            for (int ii = 0; ii < 4; ii++) a[ii] = As[ty * 4 + ii][k];
            float4 bb = *(const float4*)&Bs[k][tx * 4];
            float bv[4] = {bb.x, bb.y, bb.z, bb.w};
#pragma unroll
            for (int ii = 0; ii < 4; ii++)
#pragma unroll
                for (int jj = 0; jj < 4; jj++) acc[ii][jj] += a[ii] * bv[jj];
        }
        __syncthreads();
    }
    float* dst = g_Wpart + (size_t)blockIdx.z * (D_ * D_);
#pragma unroll
    for (int ii = 0; ii < 4; ii++) {
        int i = i0 + ty * 4 + ii;
        float4 v = make_float4(acc[ii][0], acc[ii][1], acc[ii][2], acc[ii][3]);
        *(float4*)&dst[(size_t)i * D_ + o0 + tx * 4] = v;
    }
}

// ============================================================
// reduce: W_eff = sum of 4 partials; b_eff = sum of 16 partials + b2b
// ============================================================
__global__ void reduce_k(const float* __restrict__ b2b) {
    if (blockIdx.x < 512) {
        int idx = blockIdx.x * 512 + threadIdx.x;
        g_Weff[idx] = g_Wpart[idx] + g_Wpart[262144 + idx] +
                      g_Wpart[2 * 262144 + idx] + g_Wpart[3 * 262144 + idx];
    } else {
        int c = threadIdx.x;
        float acc = b2b[c];
#pragma unroll
        for (int kz = 0; kz < 16; kz++) acc += g_beffpart[kz * D_ + c];
        g_beff[c] = acc;
    }
}

// ============================================================
// Main fused kernel: per 64-row tile
//   u = LN1(o_b + query) ; y = u @ W_eff + b_eff ;
//   out3 = LN2(u + y) + keyval_b
// 512 threads; each thread: 8 rows x 8 cols of the GEMM tile.
// ============================================================
__global__ void __launch_bounds__(512) main_k(
    const float* __restrict__ query, const float* __restrict__ keyval,
    const float* __restrict__ g1, const float* __restrict__ b1,
    const float* __restrict__ g2, const float* __restrict__ b2,
    float* __restrict__ out) {
    extern __shared__ float smem[];
    float* u_s   = smem;              // 64*512  = 32768 f
    float* ws    = u_s + 64 * 512;    // 16*512  =  8192 f
    float* o_s   = ws + 16 * 512;     // 512
    float* g1_s  = o_s + 512;         // 512
    float* b1_s  = g1_s + 512;        // 512
    float* g2_s  = b1_s + 512;        // 512
    float* b2_s  = g2_s + 512;        // 512
    float* be_s  = b2_s + 512;        // 512
    float* kv_s  = be_s + 512;        // 512
    float* red   = kv_s + 512;        // 64*4 = 256

    int t = threadIdx.x;
    int rowBase = blockIdx.x * 64;
    int b = rowBase >> 11;

    for (int i = t; i < 512; i += 512) {
        o_s[i]  = g_o[b * 512 + i];
        g1_s[i] = g1[i];
        b1_s[i] = b1[i];
        g2_s[i] = g2[i];
        b2_s[i] = b2[i];
        be_s[i] = g_beff[i];
        kv_s[i] = keyval[b * 512 + i];
    }
    __syncthreads();

    // ---------- Phase 1: u = LN1(o_b + query) ----------
    {
        int w = t >> 5, lane = t & 31;
        float4* u4 = (float4*)u_s;
        for (int rr = 0; rr < 4; rr++) {
            int r = w * 4 + rr;
            const float4* q = (const float4*)(query + (size_t)(rowBase + r) * 512);
            float4 x[4];
            float s1 = 0.f, s2 = 0.f;
#pragma unroll
            for (int j = 0; j < 4; j++) {
                int f4 = lane + 32 * j;
                float4 qq = q[f4];
                int c = f4 * 4;
                x[j].x = qq.x + o_s[c + 0];
                x[j].y = qq.y + o_s[c + 1];
                x[j].z = qq.z + o_s[c + 2];
                x[j].w = qq.w + o_s[c + 3];
                s1 += x[j].x + x[j].y + x[j].z + x[j].w;
                s2 += x[j].x * x[j].x + x[j].y * x[j].y +
                      x[j].z * x[j].z + x[j].w * x[j].w;
            }
#pragma unroll
            for (int off = 16; off; off >>= 1) {
                s1 += __shfl_xor_sync(0xffffffffu, s1, off);
                s2 += __shfl_xor_sync(0xffffffffu, s2, off);
            }
            float mean = s1 * (1.0f / 512.0f);
            float var  = s2 * (1.0f / 512.0f) - mean * mean;
            float rstd = rsqrtf(var + EPSV);
#pragma unroll
            for (int j = 0; j < 4; j++) {
                int f4 = lane + 32 * j;
                int c = f4 * 4;
                float4 uu;
                uu.x = (x[j].x - mean) * rstd * g1_s[c + 0] + b1_s[c + 0];
                uu.y = (x[j].y - mean) * rstd * g1_s[c + 1] + b1_s[c + 1];
                uu.z = (x[j].z - mean) * rstd * g1_s[c + 2] + b1_s[c + 2];
                uu.w = (x[j].w - mean) * rstd * g1_s[c + 3] + b1_s[c + 3];
                u4[r * 128 + f4] = uu;
            }
        }
    }
    __syncthreads();

    // ---------- Phase 2: y = u @ W_eff (register tile 8x8) ----------
    int tx = t & 63, ty = t >> 6;
    float acc[8][8] = {};
    for (int k0 = 0; k0 < 512; k0 += 16) {
        // stage 16x512 slice of W_eff
        const float4* Wg = (const float4*)(g_Weff + (size_t)k0 * 512);
        float4* ws4 = (float4*)ws;
#pragma unroll
        for (int i = 0; i < 4; i++) ws4[i * 512 + t] = Wg[i * 512 + t];
        __syncthreads();
#pragma unroll
        for (int kk = 0; kk < 16; kk++) {
            float ur[8], wv[8];
#pragma unroll
            for (int rr = 0; rr < 8; rr++)
                ur[rr] = u_s[(ty * 8 + rr) * 512 + k0 + kk];
#pragma unroll
            for (int cc = 0; cc < 8; cc++)
                wv[cc] = ws[kk * 512 + tx + 64 * cc];
#pragma unroll
            for (int rr = 0; rr < 8; rr++)
#pragma unroll
                for (int cc = 0; cc < 8; cc++)
                    acc[rr][cc] += ur[rr] * wv[cc];
        }
        __syncthreads();
    }

    // ---------- Phase 3: out3 = LN2(u + y + b_eff) + keyval_b ----------
    float ber[8], g2r[8], b2r[8], kvr[8];
#pragma unroll
    for (int cc = 0; cc < 8; cc++) {
        int c = tx + 64 * cc;
        ber[cc] = be_s[c]; g2r[cc] = g2_s[c]; b2r[cc] = b2_s[c]; kvr[cc] = kv_s[c];
    }
    int half = (t >> 5) & 1;
    int lane = t & 31;
#pragma unroll
    for (int rr = 0; rr < 8; rr++) {
        int r = ty * 8 + rr;
        float s1 = 0.f, s2 = 0.f;
#pragma unroll
        for (int cc = 0; cc < 8; cc++) {
            float z = u_s[r * 512 + tx + 64 * cc] + acc[rr][cc] + ber[cc];
            acc[rr][cc] = z;
            s1 += z; s2 += z * z;
        }
#pragma unroll
        for (int off = 16; off; off >>= 1) {
            s1 += __shfl_xor_sync(0xffffffffu, s1, off);
            s2 += __shfl_xor_sync(0xffffffffu, s2, off);
        }
        if (lane == 0) {
            red[r * 4 + half * 2 + 0] = s1;
            red[r * 4 + half * 2 + 1] = s2;
        }
    }
    __syncthreads();
#pragma unroll
    for (int rr = 0; rr < 8; rr++) {
        int r = ty * 8 + rr;
        float s1 = red[r * 4 + 0] + red[r * 4 + 2];
        float s2 = red[r * 4 + 1] + red[r * 4 + 3];
        float mean = s1 * (1.0f / 512.0f);
        float rstd = rsqrtf(s2 * (1.0f / 512.0f) - mean * mean + EPSV);
        size_t base = (size_t)(rowBase + r) * 512;
#pragma unroll
        for (int cc = 0; cc < 8; cc++) {
            int c = tx + 64 * cc;
            out[base + c] = (acc[rr][cc] - mean) * rstd * g2r[cc] + b2r[cc] + kvr[cc];
        }
    }
}

// ============================================================
// launch
// ============================================================
extern "C" void kernel_launch(void* const* d_in, const int* in_sizes, int n_in,
                              void* d_out, int out_size) {
    const float* query  = (const float*)d_in[0];
    const float* keyval = (const float*)d_in[1];
    // d_in[2]=Wq, d_in[3]=bq : provably unused (softmax is uniform)
    const float* Wkv = (const float*)d_in[4];
    const float* bkv = (const float*)d_in[5];
    const float* Wff = (const float*)d_in[6];
    const float* bff = (const float*)d_in[7];
    const float* g1  = (const float*)d_in[8];
    const float* b1  = (const float*)d_in[9];
    const float* W2a = (const float*)d_in[10];
    const float* b2a = (const float*)d_in[11];
    const float* W2b = (const float*)d_in[12];
    const float* b2b = (const float*)d_in[13];
    const float* g2  = (const float*)d_in[14];
    const float* b2  = (const float*)d_in[15];
    float* out = (float*)d_out;

    fill_sm<<<2048, 256>>>(out);
    compute_v<<<dim3(5, 4), 256>>>(keyval, Wkv, bkv);
    beff_part<<<16, 512>>>(b2a, W2b);
    weff_part<<<dim3(8, 8, 4), 256>>>(W2a, W2b);
    compute_o<<<dim3(2, 4), 256>>>(Wff, bff);
    reduce_k<<<513, 512>>>(b2b);

    const int smem_bytes = (64 * 512 + 16 * 512 + 7 * 512 + 256) * 4;  // 179200
    cudaFuncSetAttribute(main_k, cudaFuncAttributeMaxDynamicSharedMemorySize,
                         smem_bytes);
    main_k<<<128, 512, smem_bytes>>>(query, keyval, g1, b1, g2, b2, out);
}

// round 3
// speedup vs baseline: 1.6381x; 1.6381x over previous
#include <cuda_runtime.h>
#include <cstdint>
#include <math.h>

#define D_ 512
#define M_ 1200
#define B_ 4
#define L_ 2048
#define NROWS 8192
#define EPSV 1e-5f

#define OUT3_ELEMS (NROWS * D_)          /* 4194304  */
#define SM_ELEMS   (B_ * 6 * L_ * L_)    /* 100663296 */

// ---- static device scratch (no runtime allocations allowed) ----
__device__ float g_v[B_ * M_];
__device__ float g_o[B_ * D_];
__device__ float g_beff[D_];
__device__ float g_beffpart[16 * D_];
__device__ float g_Wpart[8 * D_ * D_];
__device__ float g_Weff[D_ * D_];        // [k][n], tf32-rounded values
__device__ float g_u[NROWS * D_];        // LN1 output, tf32-rounded
__device__ float g_z[NROWS * D_];        // u + y + beff (pre-LN2)
__device__ float g_ps1[NROWS * 4];       // per-row partial sums (4 n-chunks)
__device__ float g_ps2[NROWS * 4];

// ================= helpers =================
__device__ __forceinline__ uint32_t smem_u32(const void* p) {
    uint32_t a;
    asm("{ .reg .u64 t; cvta.to.shared.u64 t, %1; cvt.u32.u64 %0, t; }"
        : "=r"(a) : "l"(p));
    return a;
}
__device__ __forceinline__ float tf32r(float x) {
    uint32_t u;
    asm("cvt.rna.tf32.f32 %0, %1;" : "=r"(u) : "f"(x));
    return __uint_as_float(u);
}
__device__ __forceinline__ void cp16(uint32_t dst, const void* src) {
    asm volatile("cp.async.cg.shared.global [%0], [%1], 16;"
                 :: "r"(dst), "l"(src));
}
#define CP_COMMIT() asm volatile("cp.async.commit_group;" ::: "memory")
#define CP_WAIT(n)  asm volatile("cp.async.wait_group %0;" :: "n"(n) : "memory")

__device__ __forceinline__ void mma8(float* c, const float* a, const float* b) {
    asm volatile(
        "mma.sync.aligned.m16n8k8.row.col.f32.tf32.tf32.f32 "
        "{%0,%1,%2,%3}, {%4,%5,%6,%7}, {%8,%9}, {%0,%1,%2,%3};"
        : "+f"(c[0]), "+f"(c[1]), "+f"(c[2]), "+f"(c[3])
        : "r"(__float_as_uint(a[0])), "r"(__float_as_uint(a[1])),
          "r"(__float_as_uint(a[2])), "r"(__float_as_uint(a[3])),
          "r"(__float_as_uint(b[0])), "r"(__float_as_uint(b[1])));
}

// ============================================================
// sm = uniform 1/2048 exactly
// ============================================================
__global__ void fill_sm(float* __restrict__ out) {
    const float v = 1.0f / 2048.0f;
    float4 f = make_float4(v, v, v, v);
    float4* p = (float4*)(out + OUT3_ELEMS);
    int n4 = SM_ELEMS / 4;
    for (int i = blockIdx.x * blockDim.x + threadIdx.x; i < n4;
         i += gridDim.x * blockDim.x)
        p[i] = f;
}

// ============================================================
// v_b[j] = keyval[b] . Wkv[:, M+j] + bkv[M+j]
// ============================================================
__global__ void compute_v(const float* __restrict__ keyval,
                          const float* __restrict__ Wkv,
                          const float* __restrict__ bkv) {
    __shared__ float kv_s[D_];
    int b = blockIdx.y;
    for (int i = threadIdx.x; i < D_; i += blockDim.x)
        kv_s[i] = keyval[b * D_ + i];
    __syncthreads();
    int j = blockIdx.x * blockDim.x + threadIdx.x;
    if (j >= M_) return;
    const float* w = Wkv + M_ + j;
    float acc = bkv[M_ + j];
#pragma unroll 8
    for (int d = 0; d < D_; d++) acc += kv_s[d] * w[d * (2 * M_)];
    g_v[b * M_ + j] = acc;
}

// ============================================================
// o_b[c] = v_b . Wff[:, c] + bff[c]
// ============================================================
__global__ void compute_o(const float* __restrict__ Wff,
                          const float* __restrict__ bff) {
    __shared__ float v_s[M_];
    int b = blockIdx.y;
    for (int i = threadIdx.x; i < M_; i += blockDim.x)
        v_s[i] = g_v[b * M_ + i];
    __syncthreads();
    int c = blockIdx.x * blockDim.x + threadIdx.x;
    float acc = bff[c];
#pragma unroll 8
    for (int j = 0; j < M_; j++) acc += v_s[j] * Wff[j * D_ + c];
    g_o[b * D_ + c] = acc;
}

// ============================================================
// b_eff partials (split-K 16); stays exact fp32
// ============================================================
__global__ void beff_part(const float* __restrict__ b2a,
                          const float* __restrict__ W2b) {
    __shared__ float s[128];
    int kz = blockIdx.x;
    int c = threadIdx.x;
    for (int i = threadIdx.x; i < 128; i += blockDim.x)
        s[i] = b2a[kz * 128 + i];
    __syncthreads();
    float acc = 0.0f;
#pragma unroll 8
    for (int k = 0; k < 128; k++)
        acc += s[k] * W2b[(kz * 128 + k) * D_ + c];
    g_beffpart[kz * D_ + c] = acc;
}

// ============================================================
// W_eff partials, fp32, split-K 8 (grid 8x8x8)
// ============================================================
__global__ void __launch_bounds__(256) weff_part(const float* __restrict__ W2a,
                                                 const float* __restrict__ W2b) {
    __shared__ float As[64][16];
    __shared__ float Bs[16][64];
    int t = threadIdx.x;
    int tx = t & 15, ty = t >> 4;
    int i0 = blockIdx.y * 64, o0 = blockIdx.x * 64, k0 = blockIdx.z * 256;
    float acc[4][4] = {};

    for (int kt = 0; kt < 256; kt += 16) {
#pragma unroll
        for (int it = 0; it < 4; it++) {
            int i = (t >> 4) + 16 * it;
            int k = t & 15;
            As[i][k] = W2a[(size_t)(i0 + i) * 2048 + k0 + kt + k];
        }
#pragma unroll
        for (int it = 0; it < 4; it++) {
            int k = (t >> 6) + 4 * it;
            int o = t & 63;
            Bs[k][o] = W2b[(size_t)(k0 + kt + k) * D_ + o0 + o];
        }
        __syncthreads();
#pragma unroll
        for (int k = 0; k < 16; k++) {
            float a[4];
#pragma unroll
            for (int ii = 0; ii < 4; ii++) a[ii] = As[ty * 4 + ii][k];
            float4 bb = *(const float4*)&Bs[k][tx * 4];
            float bv[4] = {bb.x, bb.y, bb.z, bb.w};
#pragma unroll
            for (int ii = 0; ii < 4; ii++)
#pragma unroll
                for (int jj = 0; jj < 4; jj++) acc[ii][jj] += a[ii] * bv[jj];
        }
        __syncthreads();
    }
    float* dst = g_Wpart + (size_t)blockIdx.z * (D_ * D_);
#pragma unroll
    for (int ii = 0; ii < 4; ii++) {
        int i = i0 + ty * 4 + ii;
        float4 v = make_float4(acc[ii][0], acc[ii][1], acc[ii][2], acc[ii][3]);
        *(float4*)&dst[(size_t)i * D_ + o0 + tx * 4] = v;
    }
}

// ============================================================
// reduce: W_eff[k][c] = sum_z part (tf32-rounded); b_eff = sum + b2b
// ============================================================
__global__ void reduce_k(const float* __restrict__ b2b) {
    if (blockIdx.x < 512) {
        int k = blockIdx.x, c = threadIdx.x;
        float acc = 0.0f;
#pragma unroll
        for (int z = 0; z < 8; z++) acc += g_Wpart[z * (D_ * D_) + k * D_ + c];
        g_Weff[k * D_ + c] = tf32r(acc);
    } else {
        int c = threadIdx.x;
        float acc = b2b[c];
#pragma unroll
        for (int kz = 0; kz < 16; kz++) acc += g_beffpart[kz * D_ + c];
        g_beff[c] = acc;
    }
}

// ============================================================
// ln1: u = LN1(query + o_b), tf32-rounded, one warp per row
// ============================================================
__global__ void __launch_bounds__(256) ln1_k(const float* __restrict__ query,
                                             const float* __restrict__ g1,
                                             const float* __restrict__ b1) {
    __shared__ float o_s[D_], g1_s[D_], b1_s[D_];
    int t = threadIdx.x, wid = t >> 5, lane = t & 31;
    int row = blockIdx.x * 8 + wid;
    int b = row >> 11;
    for (int i = t; i < D_; i += 256) {
        o_s[i] = g_o[b * D_ + i];
        g1_s[i] = g1[i];
        b1_s[i] = b1[i];
    }
    __syncthreads();
    const float4* q = (const float4*)(query + (size_t)row * D_);
    float4 x[4];
    float s1 = 0.f, s2 = 0.f;
#pragma unroll
    for (int j = 0; j < 4; j++) {
        int f = lane + 32 * j;
        float4 v = q[f];
        int c = f * 4;
        x[j].x = v.x + o_s[c + 0];
        x[j].y = v.y + o_s[c + 1];
        x[j].z = v.z + o_s[c + 2];
        x[j].w = v.w + o_s[c + 3];
        s1 += x[j].x + x[j].y + x[j].z + x[j].w;
        s2 += x[j].x * x[j].x + x[j].y * x[j].y + x[j].z * x[j].z + x[j].w * x[j].w;
    }
#pragma unroll
    for (int off = 16; off; off >>= 1) {
        s1 += __shfl_xor_sync(0xffffffffu, s1, off);
        s2 += __shfl_xor_sync(0xffffffffu, s2, off);
    }
    float m = s1 * (1.0f / 512.0f);
    float rs = rsqrtf(s2 * (1.0f / 512.0f) - m * m + EPSV);
    float4* u4 = (float4*)(g_u + (size_t)row * D_);
#pragma unroll
    for (int j = 0; j < 4; j++) {
        int f = lane + 32 * j;
        int c = f * 4;
        float4 u;
        u.x = tf32r((x[j].x - m) * rs * g1_s[c + 0] + b1_s[c + 0]);
        u.y = tf32r((x[j].y - m) * rs * g1_s[c + 1] + b1_s[c + 1]);
        u.z = tf32r((x[j].z - m) * rs * g1_s[c + 2] + b1_s[c + 2]);
        u.w = tf32r((x[j].w - m) * rs * g1_s[c + 3] + b1_s[c + 3]);
        u4[f] = u;
    }
}

// ============================================================
// gemm: y = u @ W_eff via mma.sync tf32; z = u + y + beff -> g_z
// plus per-row partial LN2 sums -> g_ps1/g_ps2.
// CTA 128x128 tile, 8 warps (2M x 4N), warp tile 64x32, BK=32,
// cp.async double-buffered. grid (4, 64).
// smem floats: As 2*4608 | Bs 2*4352 | be 128 | red 1024  = 19072 f
// ============================================================
#define AS_STR 36
#define BS_STR 136
#define GEMM_SMEM (19072 * 4)

__global__ void __launch_bounds__(256, 2) gemm_k() {
    extern __shared__ float sm[];
    float* As = sm;                 // 2 * 128*36
    float* Bs = sm + 2 * 4608;      // 2 * 32*136
    float* be_s = sm + 2 * 4608 + 2 * 4352;  // 128
    float* red = be_s + 128;        // 1024: s1 [128][4] then s2 [128][4]
    uint32_t sbase = smem_u32(sm);

    int t = threadIdx.x;
    int n0 = blockIdx.x * 128, rowBase = blockIdx.y * 128;

    if (t < 128) be_s[t] = g_beff[n0 + t];

    // async tile loaders
    auto loadA = [&](int buf, int k0) {
#pragma unroll
        for (int i = 0; i < 4; i++) {
            int f = t + i * 256;          // 0..1023 float4s
            int r = f >> 3, c4 = f & 7;
            uint32_t dst = sbase + (uint32_t)(buf * 4608 + r * AS_STR + c4 * 4) * 4;
            cp16(dst, g_u + (size_t)(rowBase + r) * D_ + k0 + c4 * 4);
        }
    };
    auto loadB = [&](int buf, int k0) {
#pragma unroll
        for (int i = 0; i < 4; i++) {
            int f = t + i * 256;
            int kr = f >> 5, c4 = f & 31;
            uint32_t dst = sbase + (uint32_t)(2 * 4608 + buf * 4352 + kr * BS_STR + c4 * 4) * 4;
            cp16(dst, g_Weff + (size_t)(k0 + kr) * D_ + n0 + c4 * 4);
        }
    };

    loadA(0, 0);
    loadB(0, 0);
    CP_COMMIT();

    int wid = t >> 5;
    int wm = wid & 1, wn = wid >> 1;
    int lane = t & 31, lr = lane >> 2, lc = lane & 3;

    float acc[4][4][4] = {};

    for (int ck = 0; ck < 16; ck++) {
        int buf = ck & 1;
        if (ck < 15) {
            loadA(buf ^ 1, (ck + 1) * 32);
            loadB(buf ^ 1, (ck + 1) * 32);
            CP_COMMIT();
            CP_WAIT(1);
        } else {
            CP_WAIT(0);
        }
        __syncthreads();

        const float* Ab = As + buf * 4608;
        const float* Bb = Bs + 2 * 4608 - 2 * 4608 + 0;  // (placeholder, fixed below)
        Bb = sm + 2 * 4608 + buf * 4352;

#pragma unroll
        for (int kk = 0; kk < 32; kk += 8) {
            float a[4][4];
#pragma unroll
            for (int mf = 0; mf < 4; mf++) {
                int rb = wm * 64 + mf * 16;
                a[mf][0] = Ab[(rb + lr) * AS_STR + kk + lc];
                a[mf][1] = Ab[(rb + lr + 8) * AS_STR + kk + lc];
                a[mf][2] = Ab[(rb + lr) * AS_STR + kk + 4 + lc];
                a[mf][3] = Ab[(rb + lr + 8) * AS_STR + kk + 4 + lc];
            }
            float b[4][2];
#pragma unroll
            for (int nf = 0; nf < 4; nf++) {
                int n = wn * 32 + nf * 8 + lr;
                b[nf][0] = Bb[(kk + lc) * BS_STR + n];
                b[nf][1] = Bb[(kk + 4 + lc) * BS_STR + n];
            }
#pragma unroll
            for (int mf = 0; mf < 4; mf++)
#pragma unroll
                for (int nf = 0; nf < 4; nf++)
                    mma8(acc[mf][nf], a[mf], b[nf]);
        }
        __syncthreads();
    }

    // ---- epilogue: z = u + y + beff; per-row partial sums ----
#pragma unroll
    for (int mf = 0; mf < 4; mf++) {
#pragma unroll
        for (int j = 0; j < 2; j++) {
            int rl = wm * 64 + mf * 16 + j * 8 + lr;
            int grow = rowBase + rl;
            float s1 = 0.f, s2 = 0.f;
#pragma unroll
            for (int nf = 0; nf < 4; nf++) {
                int cl = wn * 32 + nf * 8 + lc * 2;
                int gcol = n0 + cl;
                float y0 = acc[mf][nf][j * 2 + 0];
                float y1 = acc[mf][nf][j * 2 + 1];
                float2 u2 = *(const float2*)(g_u + (size_t)grow * D_ + gcol);
                float z0 = u2.x + y0 + be_s[cl];
                float z1 = u2.y + y1 + be_s[cl + 1];
                float2 zz = make_float2(z0, z1);
                *(float2*)(g_z + (size_t)grow * D_ + gcol) = zz;
                s1 += z0 + z1;
                s2 += z0 * z0 + z1 * z1;
            }
            s1 += __shfl_xor_sync(0xffffffffu, s1, 1);
            s1 += __shfl_xor_sync(0xffffffffu, s1, 2);
            s2 += __shfl_xor_sync(0xffffffffu, s2, 1);
            s2 += __shfl_xor_sync(0xffffffffu, s2, 2);
            if (lc == 0) {
                red[rl * 4 + wn] = s1;
                red[512 + rl * 4 + wn] = s2;
            }
        }
    }
    __syncthreads();
    if (t < 128) {
        float S1 = red[t * 4] + red[t * 4 + 1] + red[t * 4 + 2] + red[t * 4 + 3];
        float S2 = red[512 + t * 4] + red[512 + t * 4 + 1] +
                   red[512 + t * 4 + 2] + red[512 + t * 4 + 3];
        g_ps1[(rowBase + t) * 4 + blockIdx.x] = S1;
        g_ps2[(rowBase + t) * 4 + blockIdx.x] = S2;
    }
}

// ============================================================
// ln2: out3 = LN2(z) + keyval_b, one warp per row
// ============================================================
__global__ void __launch_bounds__(256) ln2_k(const float* __restrict__ keyval,
                                             const float* __restrict__ g2,
                                             const float* __restrict__ b2,
                                             float* __restrict__ out) {
    int t = threadIdx.x, wid = t >> 5, lane = t & 31;
    int row = blockIdx.x * 8 + wid;
    int b = row >> 11;
    float s1 = 0.f, s2 = 0.f;
#pragma unroll
    for (int i = 0; i < 4; i++) {
        s1 += g_ps1[row * 4 + i];
        s2 += g_ps2[row * 4 + i];
    }
    float m = s1 * (1.0f / 512.0f);
    float rs = rsqrtf(s2 * (1.0f / 512.0f) - m * m + EPSV);

    const float4* z4 = (const float4*)(g_z + (size_t)row * D_);
    const float4* G4 = (const float4*)g2;
    const float4* B4 = (const float4*)b2;
    const float4* K4 = (const float4*)(keyval + (size_t)b * D_);
    float4* o4 = (float4*)(out + (size_t)row * D_);
#pragma unroll
    for (int j = 0; j < 4; j++) {
        int f = lane + 32 * j;
        float4 z = z4[f], G = G4[f], Bv = B4[f], K = K4[f];
        float4 o;
        o.x = (z.x - m) * rs * G.x + Bv.x + K.x;
        o.y = (z.y - m) * rs * G.y + Bv.y + K.y;
        o.z = (z.z - m) * rs * G.z + Bv.z + K.z;
        o.w = (z.w - m) * rs * G.w + Bv.w + K.w;
        o4[f] = o;
    }
}

// ============================================================
// launch: 3-way stream fork (fill | W-chain | u-chain) -> join -> gemm -> ln2
// ============================================================
extern "C" void kernel_launch(void* const* d_in, const int* in_sizes, int n_in,
                              void* d_out, int out_size) {
    const float* query  = (const float*)d_in[0];
    const float* keyval = (const float*)d_in[1];
    const float* Wkv = (const float*)d_in[4];
    const float* bkv = (const float*)d_in[5];
    const float* Wff = (const float*)d_in[6];
    const float* bff = (const float*)d_in[7];
    const float* g1  = (const float*)d_in[8];
    const float* b1  = (const float*)d_in[9];
    const float* W2a = (const float*)d_in[10];
    const float* b2a = (const float*)d_in[11];
    const float* W2b = (const float*)d_in[12];
    const float* b2b = (const float*)d_in[13];
    const float* g2  = (const float*)d_in[14];
    const float* b2  = (const float*)d_in[15];
    float* out = (float*)d_out;

    static cudaStream_t sF = 0, sW = 0;
    static cudaEvent_t evRoot = 0, evFill = 0, evW = 0;
    static int tried = 0;
    if (!tried) {
        tried = 1;
        if (cudaStreamCreateWithFlags(&sF, cudaStreamNonBlocking) != cudaSuccess) sF = 0;
        if (cudaStreamCreateWithFlags(&sW, cudaStreamNonBlocking) != cudaSuccess) sW = 0;
        cudaEventCreateWithFlags(&evRoot, cudaEventDisableTiming);
        cudaEventCreateWithFlags(&evFill, cudaEventDisableTiming);
        cudaEventCreateWithFlags(&evW, cudaEventDisableTiming);
        cudaFuncSetAttribute(gemm_k, cudaFuncAttributeMaxDynamicSharedMemorySize,
                             GEMM_SMEM);
    }

    bool fork = (sF != 0) && (sW != 0);
    if (fork) {
        cudaEventRecord(evRoot, 0);
        cudaStreamWaitEvent(sF, evRoot, 0);
        cudaStreamWaitEvent(sW, evRoot, 0);

        fill_sm<<<2048, 256, 0, sF>>>(out);
        cudaEventRecord(evFill, sF);

        beff_part<<<16, 512, 0, sW>>>(b2a, W2b);
        weff_part<<<dim3(8, 8, 8), 256, 0, sW>>>(W2a, W2b);
        reduce_k<<<513, 512, 0, sW>>>(b2b);
        cudaEventRecord(evW, sW);

        compute_v<<<dim3(5, 4), 256>>>(keyval, Wkv, bkv);
        compute_o<<<dim3(2, 4), 256>>>(Wff, bff);
        ln1_k<<<1024, 256>>>(query, g1, b1);

        cudaStreamWaitEvent(0, evW, 0);
        gemm_k<<<dim3(4, 64), 256, GEMM_SMEM>>>();
        ln2_k<<<1024, 256>>>(keyval, g2, b2, out);
        cudaStreamWaitEvent(0, evFill, 0);
    } else {
        fill_sm<<<2048, 256>>>(out);
        beff_part<<<16, 512>>>(b2a, W2b);
        weff_part<<<dim3(8, 8, 8), 256>>>(W2a, W2b);
        reduce_k<<<513, 512>>>(b2b);
        compute_v<<<dim3(5, 4), 256>>>(keyval, Wkv, bkv);
        compute_o<<<dim3(2, 4), 256>>>(Wff, bff);
        ln1_k<<<1024, 256>>>(query, g1, b1);
        gemm_k<<<dim3(4, 64), 256, GEMM_SMEM>>>();
        ln2_k<<<1024, 256>>>(keyval, g2, b2, out);
    }
}

// round 4
// speedup vs baseline: 1.8153x; 1.1081x over previous
#include <cuda_runtime.h>
#include <cstdint>
#include <math.h>

#define D_ 512
#define M_ 1200
#define B_ 4
#define L_ 2048
#define NROWS 8192
#define EPSV 1e-5f

#define OUT3_ELEMS (NROWS * D_)          /* 4194304  */
#define SM_ELEMS   (B_ * 6 * L_ * L_)    /* 100663296 */

// ---- static device scratch (no runtime allocations allowed) ----
__device__ float g_v[B_ * M_];
__device__ float g_o[B_ * D_];
__device__ float g_beff[D_];
__device__ float g_beffpart[16 * D_];
__device__ float g_Wpart[8 * D_ * D_];
__device__ float g_Weff[D_ * D_];        // [k][n], tf32(rna)-rounded

// ================= helpers =================
__device__ __forceinline__ uint32_t smem_u32(const void* p) {
    uint32_t a;
    asm("{ .reg .u64 t; cvta.to.shared.u64 t, %1; cvt.u32.u64 %0, t; }"
        : "=r"(a) : "l"(p));
    return a;
}
__device__ __forceinline__ float tf32r(float x) {
    uint32_t u;
    asm("cvt.rna.tf32.f32 %0, %1;" : "=r"(u) : "f"(x));
    return __uint_as_float(u);
}
__device__ __forceinline__ void cp16(uint32_t dst, const void* src) {
    asm volatile("cp.async.cg.shared.global [%0], [%1], 16;"
                 :: "r"(dst), "l"(src));
}
#define CP_COMMIT() asm volatile("cp.async.commit_group;" ::: "memory")
#define CP_WAIT(n)  asm volatile("cp.async.wait_group %0;" :: "n"(n) : "memory")

__device__ __forceinline__ void mma8(float* c, const float* a, const float* b) {
    asm volatile(
        "mma.sync.aligned.m16n8k8.row.col.f32.tf32.tf32.f32 "
        "{%0,%1,%2,%3}, {%4,%5,%6,%7}, {%8,%9}, {%0,%1,%2,%3};"
        : "+f"(c[0]), "+f"(c[1]), "+f"(c[2]), "+f"(c[3])
        : "r"(__float_as_uint(a[0])), "r"(__float_as_uint(a[1])),
          "r"(__float_as_uint(a[2])), "r"(__float_as_uint(a[3])),
          "r"(__float_as_uint(b[0])), "r"(__float_as_uint(b[1])));
}

// ============================================================
// sm = uniform 1/2048 exactly (softmax of row-constant logits)
// ============================================================
__global__ void fill_sm(float* __restrict__ out) {
    const float v = 1.0f / 2048.0f;
    float4 f = make_float4(v, v, v, v);
    float4* p = (float4*)(out + OUT3_ELEMS);
    int n4 = SM_ELEMS / 4;
    for (int i = blockIdx.x * blockDim.x + threadIdx.x; i < n4;
         i += gridDim.x * blockDim.x)
        __stcs(&p[i], f);
}

// ============================================================
// v_b[j] = keyval[b] . Wkv[:, M+j] + bkv[M+j]
// ============================================================
__global__ void compute_v(const float* __restrict__ keyval,
                          const float* __restrict__ Wkv,
                          const float* __restrict__ bkv) {
    __shared__ float kv_s[D_];
    int b = blockIdx.y;
    for (int i = threadIdx.x; i < D_; i += blockDim.x)
        kv_s[i] = keyval[b * D_ + i];
    __syncthreads();
    int j = blockIdx.x * blockDim.x + threadIdx.x;
    if (j >= M_) return;
    const float* w = Wkv + M_ + j;
    float acc = bkv[M_ + j];
#pragma unroll 8
    for (int d = 0; d < D_; d++) acc += kv_s[d] * w[d * (2 * M_)];
    g_v[b * M_ + j] = acc;
}

// ============================================================
// o_b[c] = v_b . Wff[:, c] + bff[c]
// ============================================================
__global__ void compute_o(const float* __restrict__ Wff,
                          const float* __restrict__ bff) {
    __shared__ float v_s[M_];
    int b = blockIdx.y;
    for (int i = threadIdx.x; i < M_; i += blockDim.x)
        v_s[i] = g_v[b * M_ + i];
    __syncthreads();
    int c = blockIdx.x * blockDim.x + threadIdx.x;
    float acc = bff[c];
#pragma unroll 8
    for (int j = 0; j < M_; j++) acc += v_s[j] * Wff[j * D_ + c];
    g_o[b * D_ + c] = acc;
}

// ============================================================
// b_eff partials (split-K 16); exact fp32
// ============================================================
__global__ void beff_part(const float* __restrict__ b2a,
                          const float* __restrict__ W2b) {
    __shared__ float s[128];
    int kz = blockIdx.x;
    int c = threadIdx.x;
    for (int i = threadIdx.x; i < 128; i += blockDim.x)
        s[i] = b2a[kz * 128 + i];
    __syncthreads();
    float acc = 0.0f;
#pragma unroll 8
    for (int k = 0; k < 128; k++)
        acc += s[k] * W2b[(kz * 128 + k) * D_ + c];
    g_beffpart[kz * D_ + c] = acc;
}

// ============================================================
// W_eff partials, fp32, split-K 8 (grid 8x8x8)
// ============================================================
__global__ void __launch_bounds__(256) weff_part(const float* __restrict__ W2a,
                                                 const float* __restrict__ W2b) {
    __shared__ float As[64][16];
    __shared__ float Bs[16][64];
    int t = threadIdx.x;
    int tx = t & 15, ty = t >> 4;
    int i0 = blockIdx.y * 64, o0 = blockIdx.x * 64, k0 = blockIdx.z * 256;
    float acc[4][4] = {};

    for (int kt = 0; kt < 256; kt += 16) {
#pragma unroll
        for (int it = 0; it < 4; it++) {
            int i = (t >> 4) + 16 * it;
            int k = t & 15;
            As[i][k] = W2a[(size_t)(i0 + i) * 2048 + k0 + kt + k];
        }
#pragma unroll
        for (int it = 0; it < 4; it++) {
            int k = (t >> 6) + 4 * it;
            int o = t & 63;
            Bs[k][o] = W2b[(size_t)(k0 + kt + k) * D_ + o0 + o];
        }
        __syncthreads();
#pragma unroll
        for (int k = 0; k < 16; k++) {
            float a[4];
#pragma unroll
            for (int ii = 0; ii < 4; ii++) a[ii] = As[ty * 4 + ii][k];
            float4 bb = *(const float4*)&Bs[k][tx * 4];
            float bv[4] = {bb.x, bb.y, bb.z, bb.w};
#pragma unroll
            for (int ii = 0; ii < 4; ii++)
#pragma unroll
                for (int jj = 0; jj < 4; jj++) acc[ii][jj] += a[ii] * bv[jj];
        }
        __syncthreads();
    }
    float* dst = g_Wpart + (size_t)blockIdx.z * (D_ * D_);
#pragma unroll
    for (int ii = 0; ii < 4; ii++) {
        int i = i0 + ty * 4 + ii;
        float4 v = make_float4(acc[ii][0], acc[ii][1], acc[ii][2], acc[ii][3]);
        *(float4*)&dst[(size_t)i * D_ + o0 + tx * 4] = v;
    }
}

// ============================================================
// reduce: W_eff[k][c] = sum_z part (tf32 rna); b_eff = sum + b2b
// ============================================================
__global__ void reduce_k(const float* __restrict__ b2b) {
    if (blockIdx.x < 512) {
        int k = blockIdx.x, c = threadIdx.x;
        float acc = 0.0f;
#pragma unroll
        for (int z = 0; z < 8; z++) acc += g_Wpart[z * (D_ * D_) + k * D_ + c];
        g_Weff[k * D_ + c] = tf32r(acc);
    } else {
        int c = threadIdx.x;
        float acc = b2b[c];
#pragma unroll
        for (int kz = 0; kz < 16; kz++) acc += g_beffpart[kz * D_ + c];
        g_beff[c] = acc;
    }
}

// ============================================================
// gemm_fused: per CTA 64 rows x full 512 cols, 512 threads
//   LN1(query + o_b) -> u in SMEM (exact fp32, resident)
//   y = u @ W_eff  (mma.sync tf32, B double-buffered BK=16)
//   out3 = LN2(u + y + beff) + keyval_b  (fused epilogue)
// smem floats:
//   u_s   [0, 33024)          64 rows x 516
//   Bs    [33024, 49664)      2 x 16 x 520
//   o/g1/b1/be/g2/b2/kv [49664, 53248)  7 x 512
//   red   [53248, 54272)      s1[64][8], s2[64][8]
//   mrs   [54272, 54400)      m/rs per row
// ============================================================
#define US 516
#define BSTR 520
#define BS_OFF 33024
#define C_OFF 49664
#define RED_OFF 53248
#define MRS_OFF 54272
#define GF_SMEM (54400 * 4)

__global__ void __launch_bounds__(512, 1) gemm_fused(
    const float* __restrict__ query, const float* __restrict__ keyval,
    const float* __restrict__ g1, const float* __restrict__ b1,
    const float* __restrict__ g2, const float* __restrict__ b2,
    float* __restrict__ out) {
    extern __shared__ float smf[];
    float* u_s  = smf;
    float* Bs   = smf + BS_OFF;
    float* o_s  = smf + C_OFF;
    float* g1_s = o_s + 512;
    float* b1_s = o_s + 1024;
    float* be_s = o_s + 1536;
    float* g2_s = o_s + 2048;
    float* b2_s = o_s + 2560;
    float* kv_s = o_s + 3072;
    float* red  = smf + RED_OFF;
    float* mrs  = smf + MRS_OFF;
    uint32_t sbase = smem_u32(smf);

    int t = threadIdx.x;
    int rowBase = blockIdx.x * 64;
    int b = rowBase >> 11;

    // consts
    {
        int i = t;
        o_s[i]  = g_o[b * 512 + i];
        g1_s[i] = g1[i]; b1_s[i] = b1[i];
        be_s[i] = g_beff[i];
        g2_s[i] = g2[i]; b2_s[i] = b2[i];
        kv_s[i] = keyval[b * 512 + i];
    }

    // B chunk loader (16 x 512 floats, padded stride)
    auto loadB = [&](int buf, int k0) {
#pragma unroll
        for (int i = 0; i < 4; i++) {
            int f = t + i * 512;            // 0..2047 float4 ids
            int kr = f >> 7, c4 = f & 127;
            uint32_t dst = sbase +
                (uint32_t)(BS_OFF + buf * (16 * BSTR) + kr * BSTR + c4 * 4) * 4;
            cp16(dst, g_Weff + (size_t)(k0 + kr) * 512 + c4 * 4);
        }
    };
    loadB(0, 0);  CP_COMMIT();
    loadB(1, 16); CP_COMMIT();
    __syncthreads();   // consts ready

    // ---- LN1: 8 threads per row ----
    {
        int row = t >> 3, sub = t & 7;
        const float* qr = query + (size_t)(rowBase + row) * 512;
        float s1 = 0.f, s2 = 0.f;
#pragma unroll
        for (int j = 0; j < 16; j++) {
            int c = j * 32 + sub * 4;
            float4 v = *(const float4*)(qr + c);
            v.x += o_s[c + 0]; v.y += o_s[c + 1];
            v.z += o_s[c + 2]; v.w += o_s[c + 3];
            *(float4*)(u_s + row * US + c) = v;
            s1 += v.x + v.y + v.z + v.w;
            s2 += v.x * v.x + v.y * v.y + v.z * v.z + v.w * v.w;
        }
#pragma unroll
        for (int off = 1; off < 8; off <<= 1) {
            s1 += __shfl_xor_sync(0xffffffffu, s1, off);
            s2 += __shfl_xor_sync(0xffffffffu, s2, off);
        }
        float m = s1 * (1.0f / 512.0f);
        float rs = rsqrtf(s2 * (1.0f / 512.0f) - m * m + EPSV);
#pragma unroll
        for (int j = 0; j < 16; j++) {
            int c = j * 32 + sub * 4;
            float4 v = *(const float4*)(u_s + row * US + c);
            v.x = (v.x - m) * rs * g1_s[c + 0] + b1_s[c + 0];
            v.y = (v.y - m) * rs * g1_s[c + 1] + b1_s[c + 1];
            v.z = (v.z - m) * rs * g1_s[c + 2] + b1_s[c + 2];
            v.w = (v.w - m) * rs * g1_s[c + 3] + b1_s[c + 3];
            *(float4*)(u_s + row * US + c) = v;
        }
    }

    // ---- GEMM main loop ----
    int wid = t >> 5, lane = t & 31;
    int wm = wid & 1, wn = wid >> 1;     // 2M x 8N warp grid
    int lr = lane >> 2, lc = lane & 3;

    float acc[2][8][4] = {};

    for (int ck = 0; ck < 32; ck++) {
        int buf = ck & 1;
        CP_WAIT(1);
        __syncthreads();   // also orders LN1 u_s writes on first iter
        const float* Bb = Bs + buf * (16 * BSTR);
#pragma unroll
        for (int kk = 0; kk < 16; kk += 8) {
            int kg = ck * 16 + kk;
            float a[2][4];
#pragma unroll
            for (int mf = 0; mf < 2; mf++) {
                int rb = wm * 32 + mf * 16;
                a[mf][0] = u_s[(rb + lr) * US + kg + lc];
                a[mf][1] = u_s[(rb + lr + 8) * US + kg + lc];
                a[mf][2] = u_s[(rb + lr) * US + kg + 4 + lc];
                a[mf][3] = u_s[(rb + lr + 8) * US + kg + 4 + lc];
            }
            float bf[8][2];
#pragma unroll
            for (int nf = 0; nf < 8; nf++) {
                int n = wn * 64 + nf * 8 + lr;
                bf[nf][0] = Bb[(kk + lc) * BSTR + n];
                bf[nf][1] = Bb[(kk + 4 + lc) * BSTR + n];
            }
#pragma unroll
            for (int mf = 0; mf < 2; mf++)
#pragma unroll
                for (int nf = 0; nf < 8; nf++)
                    mma8(acc[mf][nf], a[mf], bf[nf]);
        }
        __syncthreads();
        if (ck + 2 < 32) { loadB(buf, (ck + 2) * 16); CP_COMMIT(); }
    }

    // ---- Epilogue: z = u + y + beff; fused LN2; write out ----
#pragma unroll
    for (int mf = 0; mf < 2; mf++) {
#pragma unroll
        for (int j = 0; j < 2; j++) {
            int rowl = wm * 32 + mf * 16 + j * 8 + lr;
            float s1 = 0.f, s2 = 0.f;
#pragma unroll
            for (int nf = 0; nf < 8; nf++) {
                int cl = wn * 64 + nf * 8 + lc * 2;
                float z0 = acc[mf][nf][j * 2 + 0] + u_s[rowl * US + cl]     + be_s[cl];
                float z1 = acc[mf][nf][j * 2 + 1] + u_s[rowl * US + cl + 1] + be_s[cl + 1];
                acc[mf][nf][j * 2 + 0] = z0;
                acc[mf][nf][j * 2 + 1] = z1;
                s1 += z0 + z1;
                s2 += z0 * z0 + z1 * z1;
            }
            s1 += __shfl_xor_sync(0xffffffffu, s1, 1);
            s1 += __shfl_xor_sync(0xffffffffu, s1, 2);
            s2 += __shfl_xor_sync(0xffffffffu, s2, 1);
            s2 += __shfl_xor_sync(0xffffffffu, s2, 2);
            if (lc == 0) {
                red[rowl * 8 + wn] = s1;
                red[512 + rowl * 8 + wn] = s2;
            }
        }
    }
    __syncthreads();
    if (t < 64) {
        float S1 = 0.f, S2 = 0.f;
#pragma unroll
        for (int i = 0; i < 8; i++) {
            S1 += red[t * 8 + i];
            S2 += red[512 + t * 8 + i];
        }
        float m = S1 * (1.0f / 512.0f);
        mrs[t * 2 + 0] = m;
        mrs[t * 2 + 1] = rsqrtf(S2 * (1.0f / 512.0f) - m * m + EPSV);
    }
    __syncthreads();
#pragma unroll
    for (int mf = 0; mf < 2; mf++) {
#pragma unroll
        for (int j = 0; j < 2; j++) {
            int rowl = wm * 32 + mf * 16 + j * 8 + lr;
            float m = mrs[rowl * 2], rs = mrs[rowl * 2 + 1];
            size_t obase = (size_t)(rowBase + rowl) * 512;
#pragma unroll
            for (int nf = 0; nf < 8; nf++) {
                int cl = wn * 64 + nf * 8 + lc * 2;
                float2 o2;
                o2.x = (acc[mf][nf][j * 2 + 0] - m) * rs * g2_s[cl]     + b2_s[cl]     + kv_s[cl];
                o2.y = (acc[mf][nf][j * 2 + 1] - m) * rs * g2_s[cl + 1] + b2_s[cl + 1] + kv_s[cl + 1];
                *(float2*)(out + obase + cl) = o2;
            }
        }
    }
}

// ============================================================
// launch: fork(fill | weff-chain) + v,o on default -> gemm_fused
// ============================================================
extern "C" void kernel_launch(void* const* d_in, const int* in_sizes, int n_in,
                              void* d_out, int out_size) {
    const float* query  = (const float*)d_in[0];
    const float* keyval = (const float*)d_in[1];
    const float* Wkv = (const float*)d_in[4];
    const float* bkv = (const float*)d_in[5];
    const float* Wff = (const float*)d_in[6];
    const float* bff = (const float*)d_in[7];
    const float* g1  = (const float*)d_in[8];
    const float* b1  = (const float*)d_in[9];
    const float* W2a = (const float*)d_in[10];
    const float* b2a = (const float*)d_in[11];
    const float* W2b = (const float*)d_in[12];
    const float* b2b = (const float*)d_in[13];
    const float* g2  = (const float*)d_in[14];
    const float* b2  = (const float*)d_in[15];
    float* out = (float*)d_out;

    static cudaStream_t sF = 0, sW = 0;
    static cudaEvent_t evRoot = 0, evFill = 0, evW = 0;
    static int tried = 0;
    if (!tried) {
        tried = 1;
        if (cudaStreamCreateWithFlags(&sF, cudaStreamNonBlocking) != cudaSuccess) sF = 0;
        if (cudaStreamCreateWithFlags(&sW, cudaStreamNonBlocking) != cudaSuccess) sW = 0;
        cudaEventCreateWithFlags(&evRoot, cudaEventDisableTiming);
        cudaEventCreateWithFlags(&evFill, cudaEventDisableTiming);
        cudaEventCreateWithFlags(&evW, cudaEventDisableTiming);
        cudaFuncSetAttribute(gemm_fused, cudaFuncAttributeMaxDynamicSharedMemorySize,
                             GF_SMEM);
    }

    bool fork = (sF != 0) && (sW != 0);
    if (fork) {
        cudaEventRecord(evRoot, 0);
        cudaStreamWaitEvent(sF, evRoot, 0);
        cudaStreamWaitEvent(sW, evRoot, 0);

        fill_sm<<<2048, 256, 0, sF>>>(out);
        cudaEventRecord(evFill, sF);

        beff_part<<<16, 512, 0, sW>>>(b2a, W2b);
        weff_part<<<dim3(8, 8, 8), 256, 0, sW>>>(W2a, W2b);
        reduce_k<<<513, 512, 0, sW>>>(b2b);
        cudaEventRecord(evW, sW);

        compute_v<<<dim3(5, 4), 256>>>(keyval, Wkv, bkv);
        compute_o<<<dim3(2, 4), 256>>>(Wff, bff);

        cudaStreamWaitEvent(0, evW, 0);
        gemm_fused<<<128, 512, GF_SMEM>>>(query, keyval, g1, b1, g2, b2, out);
        cudaStreamWaitEvent(0, evFill, 0);
    } else {
        fill_sm<<<2048, 256>>>(out);
        beff_part<<<16, 512>>>(b2a, W2b);
        weff_part<<<dim3(8, 8, 8), 256>>>(W2a, W2b);
        reduce_k<<<513, 512>>>(b2b);
        compute_v<<<dim3(5, 4), 256>>>(keyval, Wkv, bkv);
        compute_o<<<dim3(2, 4), 256>>>(Wff, bff);
        gemm_fused<<<128, 512, GF_SMEM>>>(query, keyval, g1, b1, g2, b2, out);
    }
}